// round 8
// baseline (speedup 1.0000x reference)
#include <cuda_runtime.h>
#include <cstdint>

#define B_  8
#define H_  128
#define W_  128
#define C_  64
#define F_  128

#define SA2 72    // A smem stride: banks (tc*8+g) -> conflict-free frags
#define SB  136   // B smem stride: banks (tc*8+g) -> conflict-free frags

// scratch
__device__ float  g_offsets[B_*H_*W_*18];   // predicted offsets [B,H,W,18]
__device__ float  g_wT[576*128];            // w_out, tf32-rounded [k][n]
__device__ float  g_wOffT[3*3*18*64];       // w_off transposed [dy][dx][oc][c]
__device__ float4 g_xT[B_*16*H_*W_];        // x channel-blocked [b][c/4][y][x]

__device__ __forceinline__ uint32_t f2tf32(float f){
    uint32_t r; asm("cvt.rna.tf32.f32 %0, %1;" : "=r"(r) : "f"(f)); return r;
}
__device__ __forceinline__ void mma_tf32(float* d, const uint32_t* a, const uint32_t* bb){
    asm volatile(
      "mma.sync.aligned.m16n8k8.row.col.f32.tf32.tf32.f32 "
      "{%0,%1,%2,%3}, {%4,%5,%6,%7}, {%8,%9}, {%0,%1,%2,%3};"
      : "+f"(d[0]),"+f"(d[1]),"+f"(d[2]),"+f"(d[3])
      : "r"(a[0]),"r"(a[1]),"r"(a[2]),"r"(a[3]),"r"(bb[0]),"r"(bb[1]));
}

// ---------------------------------------------------------------------------
// Prep kernels
// ---------------------------------------------------------------------------
__global__ void prep_w_kernel(const float* __restrict__ w_out)
{
    int idx = blockIdx.x * 256 + threadIdx.x;
    if (idx < 576*128) g_wT[idx] = __uint_as_float(f2tf32(w_out[idx]));
}
// w_off [dy][dx][c][oc] -> g_wOffT [dy][dx][oc][c]
__global__ void prep_woffT_kernel(const float* __restrict__ w_off)
{
    int idx = blockIdx.x * 256 + threadIdx.x;   // 3*3*18*64 = 10368
    if (idx >= 3*3*18*64) return;
    int c    = idx & 63;
    int oc   = (idx >> 6) % 18;
    int dydx = idx / (18*64);
    g_wOffT[idx] = w_off[(dydx*64 + c)*18 + oc];
}
// x [b][y][x][c] -> g_xT [b][cb][y][x] (float4 of 4 channels)
__global__ __launch_bounds__(256) void transpose_x(const float4* __restrict__ x4)
{
    const int blk  = blockIdx.x;          // b*128 + y
    const int px   = threadIdx.x & 127;
    const int half = threadIdx.x >> 7;
    const int b = blk >> 7, y = blk & 127;
    const int pix16 = (blk * 128 + px) * 16;
    #pragma unroll
    for (int q = 0; q < 8; q++) {
        int cb = half * 8 + q;
        g_xT[((b*16 + cb) << 14) + y*128 + px] = x4[pix16 + cb];
    }
}

// ---------------------------------------------------------------------------
// Kernel 1: 3x3 SAME conv, 64 -> 18 channels, fp32 (accuracy-critical).
// w in smem as [dy][dx][oc][c] -> weight reads are uniform LDS.128 broadcasts,
// row reads are LDS.128 -> FFMA-bound instead of LDS-bound.
// ---------------------------------------------------------------------------
__global__ __launch_bounds__(128) void offset_conv_kernel(
    const float* __restrict__ x, const float* __restrict__ b_off)
{
    __shared__ float row_sh[130 * 68];
    __shared__ float w_sh[3*3*18*64];     // 41.5 KB, staged once

    const int t  = threadIdx.x;
    const int by = blockIdx.x;
    const int b  = by / H_;
    const int y  = by % H_;

    // stage all weights once (linear copy)
    for (int i = t; i < 3*3*18*64; i += 128) w_sh[i] = g_wOffT[i];

    float acc[18];
    #pragma unroll
    for (int oc = 0; oc < 18; oc++) acc[oc] = b_off[oc];

    for (int dy = 0; dy < 3; dy++) {
        __syncthreads();                 // protect previous row reads
        const int yy = y + dy - 1;
        if (t < 2) {
            const int e = (t == 0) ? 0 : 129;
            float4 z = make_float4(0.f, 0.f, 0.f, 0.f);
            #pragma unroll
            for (int c = 0; c < 64; c += 4)
                *(float4*)&row_sh[e * 68 + c] = z;
        }
        {
            float4* dst = (float4*)&row_sh[(t + 1) * 68];
            if (yy >= 0 && yy < H_) {
                const float4* src = (const float4*)&x[((b * H_ + yy) * W_ + t) * C_];
                #pragma unroll
                for (int c = 0; c < 16; c++) dst[c] = src[c];
            } else {
                float4 z = make_float4(0.f, 0.f, 0.f, 0.f);
                #pragma unroll
                for (int c = 0; c < 16; c++) dst[c] = z;
            }
        }
        __syncthreads();

        #pragma unroll
        for (int dx = 0; dx < 3; dx++) {
            const float4* rp4 = (const float4*)&row_sh[(t + dx) * 68];
            const float* wb = &w_sh[(dy*3 + dx) * 18 * 64];
            #pragma unroll 2
            for (int cg = 0; cg < 16; cg++) {
                const float4 rv = rp4[cg];
                #pragma unroll
                for (int oc = 0; oc < 18; oc++) {
                    const float4 wv = *(const float4*)&wb[oc*64 + cg*4];
                    float s = acc[oc];
                    s = fmaf(rv.x, wv.x, s);
                    s = fmaf(rv.y, wv.y, s);
                    s = fmaf(rv.z, wv.z, s);
                    s = fmaf(rv.w, wv.w, s);
                    acc[oc] = s;
                }
            }
        }
    }
    float* op = &g_offsets[((b * H_ + y) * W_ + t) * 18];
    #pragma unroll
    for (int oc = 0; oc < 18; oc++) op[oc] = acc[oc];
}

// ---------------------------------------------------------------------------
// Kernel 2: fused bilinear sampling + tf32 mma GEMM, register-pipelined.
// Block = 64 pixels x N=128. 256 threads = 8 warps (2m x 4n), warp tile 32x32.
// __launch_bounds__(256,2) -> 2 blocks/SM for cross-block latency hiding.
// Split-plane gathers keep corner regs at 16 (fits the 128-reg cap).
// ---------------------------------------------------------------------------
#define ABUF (32*SA2)                       // 2304 floats
#define BBUF (32*SB)                        // 4352 floats
#define SM2_TOTAL ((2*ABUF + 2*BBUF)*4)     // 53248 B

__global__ __launch_bounds__(256, 2) void dconv_gemm_mma(
    const float* __restrict__ b_out, float* __restrict__ out)
{
    extern __shared__ float sm[];
    float* Abuf[2] = { sm, sm + ABUF };
    float* Bbuf[2] = { sm + 2*ABUF, sm + 2*ABUF + BBUF };

    const int tid  = threadIdx.x;
    const int wid  = tid >> 5;
    const int lane = tid & 31;
    const int g  = lane >> 2;
    const int tc = lane & 3;

    const int p0 = blockIdx.x * 64;       // 64-pixel tile (half an image row)
    const int b  = p0 >> 14;
    const int y  = (p0 >> 7) & 127;
    const int x0 = p0 & 127;              // 0 or 64
    const int pm = tid & 63;              // pixel in tile
    const int h  = tid >> 6;              // 0..3 -> 8 channels each
    const int gx = x0 + pm;               // ABSOLUTE x coordinate (round-6 fix)

    const int m_base = (wid >> 2) * 32;
    const int n_base = (wid & 3) * 32;
    const float* offp = &g_offsets[(p0 + pm) * 18];

    float acc[2][4][4];
    #pragma unroll
    for (int nf = 0; nf < 4; nf++) {
        const int c0 = n_base + nf*8 + 2*tc;
        const float bz0 = __ldg(&b_out[c0]), bz1 = __ldg(&b_out[c0+1]);
        #pragma unroll
        for (int mf = 0; mf < 2; mf++) {
            acc[mf][nf][0] = bz0; acc[mf][nf][1] = bz1;
            acc[mf][nf][2] = bz0; acc[mf][nf][3] = bz1;
        }
    }

    float wa=0.f, wbv=0.f, wcv=0.f, wdv=0.f;
    int i00=0, i10=0, i01=0, i11=0;

    #define COORDS(off) { \
        float nx = fminf(fmaxf((float)gx + (off).x, 0.f), 127.f); \
        float ny = fminf(fmaxf((float)y  + (off).y, 0.f), 127.f); \
        float x0f = floorf(nx), y0f = floorf(ny); \
        float x1f = fminf(x0f + 1.f, 127.f), y1f = fminf(y0f + 1.f, 127.f); \
        float lx = nx - x0f, hx = x1f - nx; \
        float ly = ny - y0f, hy = y1f - ny; \
        wa = hx*hy; wbv = hx*ly; wcv = lx*hy; wdv = lx*ly; \
        int ix0 = (int)x0f, ix1 = (int)x1f, iy0 = (int)y0f, iy1 = (int)y1f; \
        i00 = iy0*128 + ix0;  i10 = iy1*128 + ix0; \
        i01 = iy0*128 + ix1;  i11 = iy1*128 + ix1; }

    float4 c00, c10, c01, c11;            // one 4-channel plane of corners
    float4 bst[4];                        // B chunk stage
    uint32_t vv[8];

    #define GATHER_P(chv, pl) { \
        const int cb = (b*16 + ((chv)&1)*8 + h*2 + (pl)) << 14; \
        c00 = g_xT[cb + i00]; c10 = g_xT[cb + i10]; \
        c01 = g_xT[cb + i01]; c11 = g_xT[cb + i11]; }

    #define WEIGHT_P(dst) { \
        vv[(dst)+0] = f2tf32(wa*c00.x + wbv*c10.x + wcv*c01.x + wdv*c11.x); \
        vv[(dst)+1] = f2tf32(wa*c00.y + wbv*c10.y + wcv*c01.y + wdv*c11.y); \
        vv[(dst)+2] = f2tf32(wa*c00.z + wbv*c10.z + wcv*c01.z + wdv*c11.z); \
        vv[(dst)+3] = f2tf32(wa*c00.w + wbv*c10.w + wcv*c01.w + wdv*c11.w); }

    #define BLOAD(chv) { \
        const float4* src = (const float4*)&g_wT[(chv) * 4096]; \
        bst[0] = src[tid];        bst[1] = src[tid + 256]; \
        bst[2] = src[tid + 512];  bst[3] = src[tid + 768]; }

    #define MMASTEP(s, Ab, Bb) { \
        const int k0 = (s) * 8; \
        const uint32_t* Ar0 = (const uint32_t*)&(Ab)[(k0 + tc)     * SA2]; \
        const uint32_t* Ar1 = (const uint32_t*)&(Ab)[(k0 + tc + 4) * SA2]; \
        const uint32_t* Br0 = (const uint32_t*)&(Bb)[(k0 + tc)     * SB]; \
        const uint32_t* Br1 = (const uint32_t*)&(Bb)[(k0 + tc + 4) * SB]; \
        uint32_t afr[2][4]; \
        _Pragma("unroll") \
        for (int mf = 0; mf < 2; mf++) { \
            const int m = m_base + mf*16 + g; \
            afr[mf][0] = Ar0[m];  afr[mf][1] = Ar0[m+8]; \
            afr[mf][2] = Ar1[m];  afr[mf][3] = Ar1[m+8]; \
        } \
        uint32_t bfr[4][2]; \
        _Pragma("unroll") \
        for (int nf = 0; nf < 4; nf++) { \
            const int n = n_base + nf*8 + g; \
            bfr[nf][0] = Br0[n];  bfr[nf][1] = Br1[n]; \
        } \
        _Pragma("unroll") \
        for (int mf = 0; mf < 2; mf++) \
            _Pragma("unroll") \
            for (int nf = 0; nf < 4; nf++) \
                mma_tf32(acc[mf][nf], afr[mf], bfr[nf]); }

    // ---- prologue ----
    float2 curoff  = *(const float2*)(offp + 0);
    float2 nextoff = *(const float2*)(offp + 2);
    COORDS(curoff);
    GATHER_P(0, 0);  WEIGHT_P(0);
    GATHER_P(0, 1);  WEIGHT_P(4);
    BLOAD(0);

    for (int ch = 0; ch < 18; ch++) {
        const int p = ch & 1;
        float* Ab = Abuf[p];
        float* Bb = Bbuf[p];

        // 1. store staged A(ch) + B(ch)
        #pragma unroll
        for (int j = 0; j < 2; j++) {
            const int k = h*8 + j*4;
            Ab[(k+0)*SA2 + pm] = __uint_as_float(vv[j*4+0]);
            Ab[(k+1)*SA2 + pm] = __uint_as_float(vv[j*4+1]);
            Ab[(k+2)*SA2 + pm] = __uint_as_float(vv[j*4+2]);
            Ab[(k+3)*SA2 + pm] = __uint_as_float(vv[j*4+3]);
        }
        #pragma unroll
        for (int i = 0; i < 4; i++) {
            const int idx = tid + i*256;
            *(float4*)&Bb[(idx >> 5)*SB + (idx & 31)*4] = bst[i];
        }
        __syncthreads();

        const bool more = (ch + 1 < 18);
        // 2. issue plane-0 gathers + B loads for ch+1 (hidden behind MMA)
        if (more) {
            if (((ch + 1) & 1) == 0) {
                COORDS(nextoff);
                if (ch + 1 <= 14)
                    nextoff = *(const float2*)(offp + ((ch+3) >> 1) * 2);
            }
            GATHER_P(ch + 1, 0);
            BLOAD(ch + 1);
        }

        // 3. MMA first half
        MMASTEP(0, Ab, Bb);
        MMASTEP(1, Ab, Bb);

        // 4. weight plane 0, launch plane-1 gathers
        if (more) { WEIGHT_P(0); GATHER_P(ch + 1, 1); }

        // 5. MMA second half
        MMASTEP(2, Ab, Bb);
        MMASTEP(3, Ab, Bb);

        // 6. weight plane 1
        if (more) { WEIGHT_P(4); }
    }

    // ---- epilogue ----
    #pragma unroll
    for (int mf = 0; mf < 2; mf++) {
        const int row = p0 + m_base + mf*16 + g;
        #pragma unroll
        for (int nf = 0; nf < 4; nf++) {
            const int col = n_base + nf*8 + 2*tc;
            *(float2*)&out[(size_t)row * F_ + col] =
                make_float2(acc[mf][nf][0], acc[mf][nf][1]);
            *(float2*)&out[(size_t)(row + 8) * F_ + col] =
                make_float2(acc[mf][nf][2], acc[mf][nf][3]);
        }
    }
}

// ---------------------------------------------------------------------------
extern "C" void kernel_launch(void* const* d_in, const int* in_sizes, int n_in,
                              void* d_out, int out_size)
{
    const float* x     = (const float*)d_in[0];
    const float* w_off = (const float*)d_in[1];
    const float* b_off = (const float*)d_in[2];
    const float* w_out = (const float*)d_in[3];
    const float* b_out = (const float*)d_in[4];
    float* out = (float*)d_out;

    cudaFuncSetAttribute(dconv_gemm_mma,
                         cudaFuncAttributeMaxDynamicSharedMemorySize, SM2_TOTAL);

    prep_w_kernel     <<<(576*128 + 255)/256, 256>>>(w_out);
    prep_woffT_kernel <<<(3*3*18*64 + 255)/256, 256>>>(w_off);
    transpose_x       <<<B_ * H_, 256>>>((const float4*)x);
    offset_conv_kernel<<<B_ * H_, 128>>>(x, b_off);
    dconv_gemm_mma    <<<(B_*H_*W_)/64, 256, SM2_TOTAL>>>(b_out, out);
}

// round 9
// speedup vs baseline: 1.0290x; 1.0290x over previous
#include <cuda_runtime.h>
#include <cstdint>

#define B_  8
#define H_  128
#define W_  128
#define C_  64
#define F_  128

#define SA2 72    // A smem stride: banks (tc*8+g) -> conflict-free frags
#define SB  136   // B smem stride: banks (tc*8+g) -> conflict-free frags

// scratch
__device__ float  g_offsets[B_*H_*W_*18];   // predicted offsets [B,H,W,18]
__device__ float  g_wT[576*128];            // w_out, tf32-rounded [k][n]
__device__ float2 g_wOff2[3*3*64*10];       // w_off as oc-pairs [dydx][c][10] (p>=9 zero)
__device__ float4 g_xT[B_*16*H_*W_];        // x channel-blocked [b][c/4][y][x]

__device__ __forceinline__ uint32_t f2tf32(float f){
    uint32_t r; asm("cvt.rna.tf32.f32 %0, %1;" : "=r"(r) : "f"(f)); return r;
}
__device__ __forceinline__ unsigned long long pack2(float x, float y){
    unsigned long long r;
    asm("mov.b64 %0, {%1,%2};" : "=l"(r) : "f"(x), "f"(y));
    return r;
}
__device__ __forceinline__ void ffma2(unsigned long long& acc,
                                      unsigned long long a, unsigned long long w){
    asm("fma.rn.f32x2 %0, %1, %2, %0;" : "+l"(acc) : "l"(a), "l"(w));
}
__device__ __forceinline__ void mma_tf32(float* d, const uint32_t* a, const uint32_t* bb){
    asm volatile(
      "mma.sync.aligned.m16n8k8.row.col.f32.tf32.tf32.f32 "
      "{%0,%1,%2,%3}, {%4,%5,%6,%7}, {%8,%9}, {%0,%1,%2,%3};"
      : "+f"(d[0]),"+f"(d[1]),"+f"(d[2]),"+f"(d[3])
      : "r"(a[0]),"r"(a[1]),"r"(a[2]),"r"(a[3]),"r"(bb[0]),"r"(bb[1]));
}

// ---------------------------------------------------------------------------
// Prep kernels
// ---------------------------------------------------------------------------
__global__ void prep_w_kernel(const float* __restrict__ w_out)
{
    int idx = blockIdx.x * 256 + threadIdx.x;
    if (idx < 576*128) g_wT[idx] = __uint_as_float(f2tf32(w_out[idx]));
}
// w_off [dy][dx][c][oc] -> pairs [dydx][c][10] (float2; pair p = oc 2p,2p+1)
__global__ void prep_woff2_kernel(const float* __restrict__ w_off)
{
    int idx = blockIdx.x * 256 + threadIdx.x;   // 3*3*64*10 = 5760
    if (idx >= 5760) return;
    int p    = idx % 10;
    int c    = (idx / 10) % 64;
    int dydx = idx / 640;
    float2 v = make_float2(0.f, 0.f);
    if (p < 9) {
        v.x = w_off[(dydx*64 + c)*18 + 2*p];
        v.y = w_off[(dydx*64 + c)*18 + 2*p + 1];
    }
    g_wOff2[idx] = v;
}
// x [b][y][x][c] -> g_xT [b][cb][y][x] (float4 of 4 channels)
__global__ __launch_bounds__(256) void transpose_x(const float4* __restrict__ x4)
{
    const int blk  = blockIdx.x;          // b*128 + y
    const int px   = threadIdx.x & 127;
    const int half = threadIdx.x >> 7;
    const int b = blk >> 7, y = blk & 127;
    const int pix16 = (blk * 128 + px) * 16;
    #pragma unroll
    for (int q = 0; q < 8; q++) {
        int cb = half * 8 + q;
        g_xT[((b*16 + cb) << 14) + y*128 + px] = x4[pix16 + cb];
    }
}

// ---------------------------------------------------------------------------
// Kernel 1: 3x3 SAME conv, 64 -> 18 channels, fp32 via packed f32x2 FMA.
// Row smem stride 66 (conflict-free float2); weights as padded float2 pairs
// read with uniform 16B loads. 9 f32x2 accumulators per thread.
// ---------------------------------------------------------------------------
#define ROWF   (130*66)                         // row floats
#define SM1_TOTAL ((ROWF + 5760*2) * 4)         // 80400 B

__global__ __launch_bounds__(128) void offset_conv_kernel(
    const float* __restrict__ x, const float* __restrict__ b_off)
{
    extern __shared__ float sm1[];
    float* row = sm1;                                        // [130][66]
    unsigned long long* wsh = (unsigned long long*)(sm1 + ROWF);  // 5760 u64

    const int t  = threadIdx.x;
    const int by = blockIdx.x;
    const int b  = by >> 7;
    const int y  = by & 127;

    // stage all weight pairs once
    {
        const unsigned long long* src = (const unsigned long long*)g_wOff2;
        for (int i = t; i < 5760; i += 128) wsh[i] = src[i];
    }

    unsigned long long acc[9];
    #pragma unroll
    for (int p = 0; p < 9; p++) acc[p] = pack2(b_off[2*p], b_off[2*p+1]);

    for (int dy = 0; dy < 3; dy++) {
        __syncthreads();                 // protect previous row reads
        const int yy = y + dy - 1;
        if (t < 2) {
            const int e = (t == 0) ? 0 : 129;
            float2* z = (float2*)&row[e * 66];
            #pragma unroll
            for (int i = 0; i < 32; i++) z[i] = make_float2(0.f, 0.f);
        }
        {
            float2* dst = (float2*)&row[(t + 1) * 66];
            if (yy >= 0 && yy < 128) {
                const float4* src = (const float4*)&x[((b * H_ + yy) * W_ + t) * C_];
                #pragma unroll
                for (int i = 0; i < 16; i++) {
                    float4 v = src[i];
                    dst[2*i]   = make_float2(v.x, v.y);
                    dst[2*i+1] = make_float2(v.z, v.w);
                }
            } else {
                #pragma unroll
                for (int i = 0; i < 32; i++) dst[i] = make_float2(0.f, 0.f);
            }
        }
        __syncthreads();

        #pragma unroll
        for (int dx = 0; dx < 3; dx++) {
            const unsigned long long* wdx = wsh + (dy*3 + dx) * 640;
            const float* rowp = &row[(t + dx) * 66];
            #pragma unroll 4
            for (int c = 0; c < 64; c += 2) {
                const float2 rv = *(const float2*)&rowp[c];
                const unsigned long long ax = pack2(rv.x, rv.x);
                const unsigned long long ay = pack2(rv.y, rv.y);
                const unsigned long long* wx = wdx + c * 10;
                const unsigned long long* wy = wx + 10;
                #pragma unroll
                for (int p = 0; p < 9; p++) ffma2(acc[p], ax, wx[p]);
                #pragma unroll
                for (int p = 0; p < 9; p++) ffma2(acc[p], ay, wy[p]);
            }
        }
    }

    float2* op = (float2*)&g_offsets[((b * H_ + y) * W_ + t) * 18];
    #pragma unroll
    for (int p = 0; p < 9; p++) {
        float lo, hi;
        asm("mov.b64 {%0,%1}, %2;" : "=f"(lo), "=f"(hi) : "l"(acc[p]));
        op[p] = make_float2(lo, hi);
    }
}

// ---------------------------------------------------------------------------
// Kernel 2: fused bilinear sampling + tf32 mma GEMM (round-8, unchanged)
// ---------------------------------------------------------------------------
#define ABUF (32*SA2)                       // 2304 floats
#define BBUF (32*SB)                        // 4352 floats
#define SM2_TOTAL ((2*ABUF + 2*BBUF)*4)     // 53248 B

__global__ __launch_bounds__(256, 2) void dconv_gemm_mma(
    const float* __restrict__ b_out, float* __restrict__ out)
{
    extern __shared__ float sm[];
    float* Abuf[2] = { sm, sm + ABUF };
    float* Bbuf[2] = { sm + 2*ABUF, sm + 2*ABUF + BBUF };

    const int tid  = threadIdx.x;
    const int wid  = tid >> 5;
    const int lane = tid & 31;
    const int g  = lane >> 2;
    const int tc = lane & 3;

    const int p0 = blockIdx.x * 64;
    const int b  = p0 >> 14;
    const int y  = (p0 >> 7) & 127;
    const int x0 = p0 & 127;
    const int pm = tid & 63;
    const int h  = tid >> 6;
    const int gx = x0 + pm;

    const int m_base = (wid >> 2) * 32;
    const int n_base = (wid & 3) * 32;
    const float* offp = &g_offsets[(p0 + pm) * 18];

    float acc[2][4][4];
    #pragma unroll
    for (int nf = 0; nf < 4; nf++) {
        const int c0 = n_base + nf*8 + 2*tc;
        const float bz0 = __ldg(&b_out[c0]), bz1 = __ldg(&b_out[c0+1]);
        #pragma unroll
        for (int mf = 0; mf < 2; mf++) {
            acc[mf][nf][0] = bz0; acc[mf][nf][1] = bz1;
            acc[mf][nf][2] = bz0; acc[mf][nf][3] = bz1;
        }
    }

    float wa=0.f, wbv=0.f, wcv=0.f, wdv=0.f;
    int i00=0, i10=0, i01=0, i11=0;

    #define COORDS(off) { \
        float nx = fminf(fmaxf((float)gx + (off).x, 0.f), 127.f); \
        float ny = fminf(fmaxf((float)y  + (off).y, 0.f), 127.f); \
        float x0f = floorf(nx), y0f = floorf(ny); \
        float x1f = fminf(x0f + 1.f, 127.f), y1f = fminf(y0f + 1.f, 127.f); \
        float lx = nx - x0f, hx = x1f - nx; \
        float ly = ny - y0f, hy = y1f - ny; \
        wa = hx*hy; wbv = hx*ly; wcv = lx*hy; wdv = lx*ly; \
        int ix0 = (int)x0f, ix1 = (int)x1f, iy0 = (int)y0f, iy1 = (int)y1f; \
        i00 = iy0*128 + ix0;  i10 = iy1*128 + ix0; \
        i01 = iy0*128 + ix1;  i11 = iy1*128 + ix1; }

    float4 c00, c10, c01, c11;
    float4 bst[4];
    uint32_t vv[8];

    #define GATHER_P(chv, pl) { \
        const int cb = (b*16 + ((chv)&1)*8 + h*2 + (pl)) << 14; \
        c00 = g_xT[cb + i00]; c10 = g_xT[cb + i10]; \
        c01 = g_xT[cb + i01]; c11 = g_xT[cb + i11]; }

    #define WEIGHT_P(dst) { \
        vv[(dst)+0] = f2tf32(wa*c00.x + wbv*c10.x + wcv*c01.x + wdv*c11.x); \
        vv[(dst)+1] = f2tf32(wa*c00.y + wbv*c10.y + wcv*c01.y + wdv*c11.y); \
        vv[(dst)+2] = f2tf32(wa*c00.z + wbv*c10.z + wcv*c01.z + wdv*c11.z); \
        vv[(dst)+3] = f2tf32(wa*c00.w + wbv*c10.w + wcv*c01.w + wdv*c11.w); }

    #define BLOAD(chv) { \
        const float4* src = (const float4*)&g_wT[(chv) * 4096]; \
        bst[0] = src[tid];        bst[1] = src[tid + 256]; \
        bst[2] = src[tid + 512];  bst[3] = src[tid + 768]; }

    #define MMASTEP(s, Ab, Bb) { \
        const int k0 = (s) * 8; \
        const uint32_t* Ar0 = (const uint32_t*)&(Ab)[(k0 + tc)     * SA2]; \
        const uint32_t* Ar1 = (const uint32_t*)&(Ab)[(k0 + tc + 4) * SA2]; \
        const uint32_t* Br0 = (const uint32_t*)&(Bb)[(k0 + tc)     * SB]; \
        const uint32_t* Br1 = (const uint32_t*)&(Bb)[(k0 + tc + 4) * SB]; \
        uint32_t afr[2][4]; \
        _Pragma("unroll") \
        for (int mf = 0; mf < 2; mf++) { \
            const int m = m_base + mf*16 + g; \
            afr[mf][0] = Ar0[m];  afr[mf][1] = Ar0[m+8]; \
            afr[mf][2] = Ar1[m];  afr[mf][3] = Ar1[m+8]; \
        } \
        uint32_t bfr[4][2]; \
        _Pragma("unroll") \
        for (int nf = 0; nf < 4; nf++) { \
            const int n = n_base + nf*8 + g; \
            bfr[nf][0] = Br0[n];  bfr[nf][1] = Br1[n]; \
        } \
        _Pragma("unroll") \
        for (int mf = 0; mf < 2; mf++) \
            _Pragma("unroll") \
            for (int nf = 0; nf < 4; nf++) \
                mma_tf32(acc[mf][nf], afr[mf], bfr[nf]); }

    // ---- prologue ----
    float2 curoff  = *(const float2*)(offp + 0);
    float2 nextoff = *(const float2*)(offp + 2);
    COORDS(curoff);
    GATHER_P(0, 0);  WEIGHT_P(0);
    GATHER_P(0, 1);  WEIGHT_P(4);
    BLOAD(0);

    for (int ch = 0; ch < 18; ch++) {
        const int p = ch & 1;
        float* Ab = Abuf[p];
        float* Bb = Bbuf[p];

        #pragma unroll
        for (int j = 0; j < 2; j++) {
            const int k = h*8 + j*4;
            Ab[(k+0)*SA2 + pm] = __uint_as_float(vv[j*4+0]);
            Ab[(k+1)*SA2 + pm] = __uint_as_float(vv[j*4+1]);
            Ab[(k+2)*SA2 + pm] = __uint_as_float(vv[j*4+2]);
            Ab[(k+3)*SA2 + pm] = __uint_as_float(vv[j*4+3]);
        }
        #pragma unroll
        for (int i = 0; i < 4; i++) {
            const int idx = tid + i*256;
            *(float4*)&Bb[(idx >> 5)*SB + (idx & 31)*4] = bst[i];
        }
        __syncthreads();

        const bool more = (ch + 1 < 18);
        if (more) {
            if (((ch + 1) & 1) == 0) {
                COORDS(nextoff);
                if (ch + 1 <= 14)
                    nextoff = *(const float2*)(offp + ((ch+3) >> 1) * 2);
            }
            GATHER_P(ch + 1, 0);
            BLOAD(ch + 1);
        }

        MMASTEP(0, Ab, Bb);
        MMASTEP(1, Ab, Bb);
        if (more) { WEIGHT_P(0); GATHER_P(ch + 1, 1); }
        MMASTEP(2, Ab, Bb);
        MMASTEP(3, Ab, Bb);
        if (more) { WEIGHT_P(4); }
    }

    #pragma unroll
    for (int mf = 0; mf < 2; mf++) {
        const int row = p0 + m_base + mf*16 + g;
        #pragma unroll
        for (int nf = 0; nf < 4; nf++) {
            const int col = n_base + nf*8 + 2*tc;
            *(float2*)&out[(size_t)row * F_ + col] =
                make_float2(acc[mf][nf][0], acc[mf][nf][1]);
            *(float2*)&out[(size_t)(row + 8) * F_ + col] =
                make_float2(acc[mf][nf][2], acc[mf][nf][3]);
        }
    }
}

// ---------------------------------------------------------------------------
extern "C" void kernel_launch(void* const* d_in, const int* in_sizes, int n_in,
                              void* d_out, int out_size)
{
    const float* x     = (const float*)d_in[0];
    const float* w_off = (const float*)d_in[1];
    const float* b_off = (const float*)d_in[2];
    const float* w_out = (const float*)d_in[3];
    const float* b_out = (const float*)d_in[4];
    float* out = (float*)d_out;

    cudaFuncSetAttribute(offset_conv_kernel,
                         cudaFuncAttributeMaxDynamicSharedMemorySize, SM1_TOTAL);
    cudaFuncSetAttribute(dconv_gemm_mma,
                         cudaFuncAttributeMaxDynamicSharedMemorySize, SM2_TOTAL);

    prep_w_kernel     <<<(576*128 + 255)/256, 256>>>(w_out);
    prep_woff2_kernel <<<(5760 + 255)/256, 256>>>(w_off);
    transpose_x       <<<B_ * H_, 256>>>((const float4*)x);
    offset_conv_kernel<<<B_ * H_, 128, SM1_TOTAL>>>(x, b_off);
    dconv_gemm_mma    <<<(B_*H_*W_)/64, 256, SM2_TOTAL>>>(b_out, out);
}

// round 10
// speedup vs baseline: 1.1034x; 1.0724x over previous
#include <cuda_runtime.h>
#include <cstdint>

#define B_  8
#define H_  128
#define W_  128
#define C_  64
#define F_  128

#define SA2 72    // A smem stride: banks (tc*8+g) -> conflict-free frags
#define SB  136   // B smem stride: banks (tc*8+g) -> conflict-free frags
#define BBUF (32*SB)                        // 4352 floats per B chunk (padded)
#define ABUF (32*SA2)                       // 2304 floats

// scratch
__device__ float  g_offsets[B_*H_*W_*18];   // predicted offsets [B,H,W,18]
__device__ float  g_wTp[18*BBUF];           // w_out tf32, pre-padded [ch][kk*SB+n]
__device__ float2 g_wOff2[3*3*64*10];       // w_off as oc-pairs [dydx][c][10]
__device__ float4 g_xT[B_*16*H_*W_];        // x channel-blocked [b][c/4][y][x]

__device__ __forceinline__ uint32_t f2tf32(float f){
    uint32_t r; asm("cvt.rna.tf32.f32 %0, %1;" : "=r"(r) : "f"(f)); return r;
}
__device__ __forceinline__ unsigned long long pack2(float x, float y){
    unsigned long long r;
    asm("mov.b64 %0, {%1,%2};" : "=l"(r) : "f"(x), "f"(y));
    return r;
}
__device__ __forceinline__ void ffma2(unsigned long long& acc,
                                      unsigned long long a, unsigned long long w){
    asm("fma.rn.f32x2 %0, %1, %2, %0;" : "+l"(acc) : "l"(a), "l"(w));
}
__device__ __forceinline__ void addf2(unsigned long long& acc, unsigned long long v){
    asm("add.rn.f32x2 %0, %1, %2;" : "=l"(acc) : "l"(acc), "l"(v));
}
__device__ __forceinline__ uint32_t smem_u32(const void* p){
    uint32_t a;
    asm("{ .reg .u64 t; cvta.to.shared.u64 t, %1; cvt.u32.u64 %0, t; }":"=r"(a):"l"(p));
    return a;
}
__device__ __forceinline__ void cpasync16(uint32_t dst, const void* src){
    asm volatile("cp.async.cg.shared.global [%0], [%1], 16;"::"r"(dst),"l"(src):"memory");
}
#define CP_COMMIT() asm volatile("cp.async.commit_group;":::"memory")
#define CP_WAIT0()  asm volatile("cp.async.wait_group 0;":::"memory")

__device__ __forceinline__ void mma_tf32(float* d, const uint32_t* a, const uint32_t* bb){
    asm volatile(
      "mma.sync.aligned.m16n8k8.row.col.f32.tf32.tf32.f32 "
      "{%0,%1,%2,%3}, {%4,%5,%6,%7}, {%8,%9}, {%0,%1,%2,%3};"
      : "+f"(d[0]),"+f"(d[1]),"+f"(d[2]),"+f"(d[3])
      : "r"(a[0]),"r"(a[1]),"r"(a[2]),"r"(a[3]),"r"(bb[0]),"r"(bb[1]));
}

// ---------------------------------------------------------------------------
// Prep kernels
// ---------------------------------------------------------------------------
// w_out [576][128] -> tf32, padded layout [ch][kk*SB + n] (n>=128 zero)
__global__ void prep_wp_kernel(const float* __restrict__ w_out)
{
    int idx = blockIdx.x * 256 + threadIdx.x;   // 18*BBUF = 78336
    if (idx >= 18*BBUF) return;
    int n  = idx % SB;
    int kk = (idx / SB) & 31;
    int ch = idx / BBUF;
    float v = 0.f;
    if (n < 128) v = __uint_as_float(f2tf32(w_out[(ch*32 + kk)*128 + n]));
    g_wTp[idx] = v;
}
// w_off [dy][dx][c][oc] -> pairs [dydx][c][10]
__global__ void prep_woff2_kernel(const float* __restrict__ w_off)
{
    int idx = blockIdx.x * 256 + threadIdx.x;   // 5760
    if (idx >= 5760) return;
    int p    = idx % 10;
    int c    = (idx / 10) % 64;
    int dydx = idx / 640;
    float2 v = make_float2(0.f, 0.f);
    if (p < 9) {
        v.x = w_off[(dydx*64 + c)*18 + 2*p];
        v.y = w_off[(dydx*64 + c)*18 + 2*p + 1];
    }
    g_wOff2[idx] = v;
}
// x [b][y][x][c] -> g_xT [b][cb][y][x]
__global__ __launch_bounds__(256) void transpose_x(const float4* __restrict__ x4)
{
    const int blk  = blockIdx.x;
    const int px   = threadIdx.x & 127;
    const int half = threadIdx.x >> 7;
    const int b = blk >> 7, y = blk & 127;
    const int pix16 = (blk * 128 + px) * 16;
    #pragma unroll
    for (int q = 0; q < 8; q++) {
        int cb = half * 8 + q;
        g_xT[((b*16 + cb) << 14) + y*128 + px] = x4[pix16 + cb];
    }
}

// ---------------------------------------------------------------------------
// Kernel 1: 3x3 SAME conv 64->18, fp32 f32x2, channel-split across 2 halves.
// 256 threads: (pm, th) = pixel, channel-half. Partial sums reduced via smem.
// ---------------------------------------------------------------------------
#define ROWF   (130*66)
#define SM1_TOTAL ((ROWF + 5760*2) * 4)         // 80400 B

__global__ __launch_bounds__(256) void offset_conv_kernel(
    const float* __restrict__ x, const float* __restrict__ b_off)
{
    extern __shared__ float sm1[];
    float* row = sm1;                                        // [130][66]
    unsigned long long* wsh = (unsigned long long*)(sm1 + ROWF);

    const int t  = threadIdx.x;
    const int pm = t & 127;
    const int th = t >> 7;                 // channel half: 0 -> c<32, 1 -> c>=32
    const int by = blockIdx.x;
    const int b  = by >> 7;
    const int y  = by & 127;

    {
        const unsigned long long* src = (const unsigned long long*)g_wOff2;
        for (int i = t; i < 5760; i += 256) wsh[i] = src[i];
    }

    unsigned long long acc[9];
    #pragma unroll
    for (int p = 0; p < 9; p++)
        acc[p] = th ? pack2(0.f, 0.f) : pack2(b_off[2*p], b_off[2*p+1]);

    for (int dy = 0; dy < 3; dy++) {
        __syncthreads();
        const int yy = y + dy - 1;
        if (t < 2) {                       // zero horizontal pads (full 64 ch)
            const int e = (t == 0) ? 0 : 129;
            float2* z = (float2*)&row[e * 66];
            #pragma unroll
            for (int i = 0; i < 32; i++) z[i] = make_float2(0.f, 0.f);
        }
        {
            float2* dst = (float2*)&row[(pm + 1) * 66] + th * 16;
            if (yy >= 0 && yy < 128) {
                const float4* src =
                    (const float4*)&x[((b * H_ + yy) * W_ + pm) * C_ + th * 32];
                #pragma unroll
                for (int i = 0; i < 8; i++) {
                    float4 v = src[i];
                    dst[2*i]   = make_float2(v.x, v.y);
                    dst[2*i+1] = make_float2(v.z, v.w);
                }
            } else {
                #pragma unroll
                for (int i = 0; i < 16; i++) dst[i] = make_float2(0.f, 0.f);
            }
        }
        __syncthreads();

        #pragma unroll
        for (int dx = 0; dx < 3; dx++) {
            const float* rowp = &row[(pm + dx) * 66 + th * 32];
            const unsigned long long* wdx = wsh + (dy*3 + dx) * 640 + th * 320;
            #pragma unroll 4
            for (int c = 0; c < 32; c += 2) {
                const float2 rv = *(const float2*)&rowp[c];
                const unsigned long long ax = pack2(rv.x, rv.x);
                const unsigned long long ay = pack2(rv.y, rv.y);
                const unsigned long long* wx = wdx + c * 10;
                const unsigned long long* wy = wx + 10;
                #pragma unroll
                for (int p = 0; p < 9; p++) ffma2(acc[p], ax, wx[p]);
                #pragma unroll
                for (int p = 0; p < 9; p++) ffma2(acc[p], ay, wy[p]);
            }
        }
    }

    // cross-half reduction (reuse row area)
    __syncthreads();
    unsigned long long* red = (unsigned long long*)row;   // 128*10 u64
    if (th == 1) {
        #pragma unroll
        for (int p = 0; p < 9; p++) red[pm*10 + p] = acc[p];
    }
    __syncthreads();
    if (th == 0) {
        float2* op = (float2*)&g_offsets[((b * H_ + y) * W_ + pm) * 18];
        #pragma unroll
        for (int p = 0; p < 9; p++) {
            addf2(acc[p], red[pm*10 + p]);
            float lo, hi;
            asm("mov.b64 {%0,%1}, %2;" : "=f"(lo), "=f"(hi) : "l"(acc[p]));
            op[p] = make_float2(lo, hi);
        }
    }
}

// ---------------------------------------------------------------------------
// Kernel 2: fused bilinear sampling + tf32 mma GEMM.
// Block = 64 px x N=128, 256 thr, 2 blocks/SM. B staged via cp.async.cg from
// pre-padded g_wTp (linear 17KB copies). Both gather planes issued right
// after the sync; weighted after the full MMA phase.
// ---------------------------------------------------------------------------
#define SM2_TOTAL ((2*ABUF + 2*BBUF)*4)     // 53248 B

__global__ __launch_bounds__(256, 2) void dconv_gemm_mma(
    const float* __restrict__ b_out, float* __restrict__ out)
{
    extern __shared__ float sm[];
    float* Abuf[2] = { sm, sm + ABUF };
    float* Bbuf[2] = { sm + 2*ABUF, sm + 2*ABUF + BBUF };
    const uint32_t Bu = smem_u32(sm + 2*ABUF);

    const int tid  = threadIdx.x;
    const int wid  = tid >> 5;
    const int lane = tid & 31;
    const int g  = lane >> 2;
    const int tc = lane & 3;

    const int p0 = blockIdx.x * 64;
    const int b  = p0 >> 14;
    const int y  = (p0 >> 7) & 127;
    const int x0 = p0 & 127;
    const int pm = tid & 63;
    const int h  = tid >> 6;
    const int gx = x0 + pm;

    const int m_base = (wid >> 2) * 32;
    const int n_base = (wid & 3) * 32;
    const float* offp = &g_offsets[(p0 + pm) * 18];

    float acc[2][4][4];
    #pragma unroll
    for (int nf = 0; nf < 4; nf++) {
        const int c0 = n_base + nf*8 + 2*tc;
        const float bz0 = __ldg(&b_out[c0]), bz1 = __ldg(&b_out[c0+1]);
        #pragma unroll
        for (int mf = 0; mf < 2; mf++) {
            acc[mf][nf][0] = bz0; acc[mf][nf][1] = bz1;
            acc[mf][nf][2] = bz0; acc[mf][nf][3] = bz1;
        }
    }

    float wa=0.f, wbv=0.f, wcv=0.f, wdv=0.f;
    int i00=0, i10=0, i01=0, i11=0;

    #define COORDS(off) { \
        float nx = fminf(fmaxf((float)gx + (off).x, 0.f), 127.f); \
        float ny = fminf(fmaxf((float)y  + (off).y, 0.f), 127.f); \
        float x0f = floorf(nx), y0f = floorf(ny); \
        float x1f = fminf(x0f + 1.f, 127.f), y1f = fminf(y0f + 1.f, 127.f); \
        float lx = nx - x0f, hx = x1f - nx; \
        float ly = ny - y0f, hy = y1f - ny; \
        wa = hx*hy; wbv = hx*ly; wcv = lx*hy; wdv = lx*ly; \
        int ix0 = (int)x0f, ix1 = (int)x1f, iy0 = (int)y0f, iy1 = (int)y1f; \
        i00 = iy0*128 + ix0;  i10 = iy1*128 + ix0; \
        i01 = iy0*128 + ix1;  i11 = iy1*128 + ix1; }

    float4 a0,b0,c0_,d0, a1,b1,c1_,d1;     // both planes of corners
    uint32_t vv[8];

    #define GATHER2(chv) { \
        const int cb = (b*16 + ((chv)&1)*8 + h*2) << 14; \
        a0 = g_xT[cb + i00]; b0 = g_xT[cb + i10]; \
        c0_ = g_xT[cb + i01]; d0 = g_xT[cb + i11]; \
        const int cb1 = cb + (1 << 14); \
        a1 = g_xT[cb1 + i00]; b1 = g_xT[cb1 + i10]; \
        c1_ = g_xT[cb1 + i01]; d1 = g_xT[cb1 + i11]; }

    #define WEIGHT2() { \
        vv[0] = f2tf32(wa*a0.x + wbv*b0.x + wcv*c0_.x + wdv*d0.x); \
        vv[1] = f2tf32(wa*a0.y + wbv*b0.y + wcv*c0_.y + wdv*d0.y); \
        vv[2] = f2tf32(wa*a0.z + wbv*b0.z + wcv*c0_.z + wdv*d0.z); \
        vv[3] = f2tf32(wa*a0.w + wbv*b0.w + wcv*c0_.w + wdv*d0.w); \
        vv[4] = f2tf32(wa*a1.x + wbv*b1.x + wcv*c1_.x + wdv*d1.x); \
        vv[5] = f2tf32(wa*a1.y + wbv*b1.y + wcv*c1_.y + wdv*d1.y); \
        vv[6] = f2tf32(wa*a1.z + wbv*b1.z + wcv*c1_.z + wdv*d1.z); \
        vv[7] = f2tf32(wa*a1.w + wbv*b1.w + wcv*c1_.w + wdv*d1.w); }

    #define CPB(chv, pbuf) { \
        const uint32_t dbase = Bu + (uint32_t)(pbuf) * (BBUF*4u); \
        const char* srcb = (const char*)&g_wTp[(chv) * BBUF]; \
        _Pragma("unroll") \
        for (int i = 0; i < 5; i++) { \
            int idx = tid + i*256; \
            if (idx < 1088) cpasync16(dbase + (uint32_t)idx*16u, srcb + idx*16); \
        } }

    #define MMASTEP(s, Ab, Bb) { \
        const int k0 = (s) * 8; \
        const uint32_t* Ar0 = (const uint32_t*)&(Ab)[(k0 + tc)     * SA2]; \
        const uint32_t* Ar1 = (const uint32_t*)&(Ab)[(k0 + tc + 4) * SA2]; \
        const uint32_t* Br0 = (const uint32_t*)&(Bb)[(k0 + tc)     * SB]; \
        const uint32_t* Br1 = (const uint32_t*)&(Bb)[(k0 + tc + 4) * SB]; \
        uint32_t afr[2][4]; \
        _Pragma("unroll") \
        for (int mf = 0; mf < 2; mf++) { \
            const int m = m_base + mf*16 + g; \
            afr[mf][0] = Ar0[m];  afr[mf][1] = Ar0[m+8]; \
            afr[mf][2] = Ar1[m];  afr[mf][3] = Ar1[m+8]; \
        } \
        uint32_t bfr[4][2]; \
        _Pragma("unroll") \
        for (int nf = 0; nf < 4; nf++) { \
            const int n = n_base + nf*8 + g; \
            bfr[nf][0] = Br0[n];  bfr[nf][1] = Br1[n]; \
        } \
        _Pragma("unroll") \
        for (int mf = 0; mf < 2; mf++) \
            _Pragma("unroll") \
            for (int nf = 0; nf < 4; nf++) \
                mma_tf32(acc[mf][nf], afr[mf], bfr[nf]); }

    // ---- prologue ----
    float2 curoff  = *(const float2*)(offp + 0);
    float2 nextoff = *(const float2*)(offp + 2);
    COORDS(curoff);
    GATHER2(0);
    WEIGHT2();                      // vv = A(0); stalls on first gathers only
    CPB(0, 0); CP_COMMIT();         // B(0) in flight

    for (int ch = 0; ch < 18; ch++) {
        const int p = ch & 1;
        float* Ab = Abuf[p];
        float* Bb = Bbuf[p];

        // 1. store A(ch) from vv
        #pragma unroll
        for (int j = 0; j < 2; j++) {
            const int k = h*8 + j*4;
            Ab[(k+0)*SA2 + pm] = __uint_as_float(vv[j*4+0]);
            Ab[(k+1)*SA2 + pm] = __uint_as_float(vv[j*4+1]);
            Ab[(k+2)*SA2 + pm] = __uint_as_float(vv[j*4+2]);
            Ab[(k+3)*SA2 + pm] = __uint_as_float(vv[j*4+3]);
        }

        // 2. B(ch) must have landed; publish A(ch)+B(ch)
        CP_WAIT0();
        __syncthreads();

        const bool more = (ch + 1 < 18);
        // 3. issue next chunk's gathers + B copy (hidden behind MMA phase)
        if (more) {
            if (((ch + 1) & 1) == 0) {
                COORDS(nextoff);
                if (ch + 1 <= 14)
                    nextoff = *(const float2*)(offp + ((ch+3) >> 1) * 2);
            }
            GATHER2(ch + 1);
            CPB(ch + 1, p ^ 1); CP_COMMIT();
        }

        // 4. full MMA phase on chunk ch
        MMASTEP(0, Ab, Bb);
        MMASTEP(1, Ab, Bb);
        MMASTEP(2, Ab, Bb);
        MMASTEP(3, Ab, Bb);

        // 5. weight+convert next chunk's samples
        if (more) { WEIGHT2(); }
    }

    // ---- epilogue ----
    #pragma unroll
    for (int mf = 0; mf < 2; mf++) {
        const int row = p0 + m_base + mf*16 + g;
        #pragma unroll
        for (int nf = 0; nf < 4; nf++) {
            const int col = n_base + nf*8 + 2*tc;
            *(float2*)&out[(size_t)row * F_ + col] =
                make_float2(acc[mf][nf][0], acc[mf][nf][1]);
            *(float2*)&out[(size_t)(row + 8) * F_ + col] =
                make_float2(acc[mf][nf][2], acc[mf][nf][3]);
        }
    }
}

// ---------------------------------------------------------------------------
extern "C" void kernel_launch(void* const* d_in, const int* in_sizes, int n_in,
                              void* d_out, int out_size)
{
    const float* x     = (const float*)d_in[0];
    const float* w_off = (const float*)d_in[1];
    const float* b_off = (const float*)d_in[2];
    const float* w_out = (const float*)d_in[3];
    const float* b_out = (const float*)d_in[4];
    float* out = (float*)d_out;

    cudaFuncSetAttribute(offset_conv_kernel,
                         cudaFuncAttributeMaxDynamicSharedMemorySize, SM1_TOTAL);
    cudaFuncSetAttribute(dconv_gemm_mma,
                         cudaFuncAttributeMaxDynamicSharedMemorySize, SM2_TOTAL);

    prep_wp_kernel    <<<(18*BBUF + 255)/256, 256>>>(w_out);
    prep_woff2_kernel <<<(5760 + 255)/256, 256>>>(w_off);
    transpose_x       <<<B_ * H_, 256>>>((const float4*)x);
    offset_conv_kernel<<<B_ * H_, 256, SM1_TOTAL>>>(x, b_off);
    dconv_gemm_mma    <<<(B_*H_*W_)/64, 256, SM2_TOTAL>>>(b_out, out);
}

// round 11
// speedup vs baseline: 1.1674x; 1.0580x over previous
#include <cuda_runtime.h>
#include <cstdint>

#define B_  8
#define H_  128
#define W_  128
#define C_  64
#define F_  128

#define SA2 72    // A smem stride: banks (tc*8+g) -> conflict-free frags
#define SB  136   // B smem stride: banks (tc*8+g) -> conflict-free frags
#define BBUF (32*SB)                        // 4352 floats per B chunk (padded)
#define ABUF (32*SA2)                       // 2304 floats

// scratch
__device__ float  g_offsets[B_*H_*W_*18];   // predicted offsets [B,H,W,18]
__device__ float  g_wTp[18*BBUF];           // w_out tf32, pre-padded [ch][kk*SB+n]
__device__ float2 g_wOff2[3*3*64*10];       // w_off as oc-pairs [dydx][c][10]
__device__ float4 g_xT[B_*16*H_*W_];        // x channel-blocked [b][c/4][y][x]

__device__ __forceinline__ uint32_t f2tf32(float f){
    uint32_t r; asm("cvt.rna.tf32.f32 %0, %1;" : "=r"(r) : "f"(f)); return r;
}
__device__ __forceinline__ unsigned long long pack2(float x, float y){
    unsigned long long r;
    asm("mov.b64 %0, {%1,%2};" : "=l"(r) : "f"(x), "f"(y));
    return r;
}
__device__ __forceinline__ void ffma2(unsigned long long& acc,
                                      unsigned long long a, unsigned long long w){
    asm("fma.rn.f32x2 %0, %1, %2, %0;" : "+l"(acc) : "l"(a), "l"(w));
}
__device__ __forceinline__ void addf2(unsigned long long& acc, unsigned long long v){
    asm("add.rn.f32x2 %0, %1, %2;" : "=l"(acc) : "l"(acc), "l"(v));
}
__device__ __forceinline__ uint32_t smem_u32(const void* p){
    uint32_t a;
    asm("{ .reg .u64 t; cvta.to.shared.u64 t, %1; cvt.u32.u64 %0, t; }":"=r"(a):"l"(p));
    return a;
}
__device__ __forceinline__ void cpasync16(uint32_t dst, const void* src){
    asm volatile("cp.async.cg.shared.global [%0], [%1], 16;"::"r"(dst),"l"(src):"memory");
}
#define CP_COMMIT() asm volatile("cp.async.commit_group;":::"memory")
#define CP_WAIT0()  asm volatile("cp.async.wait_group 0;":::"memory")

__device__ __forceinline__ void mma_tf32(float* d, const uint32_t* a, const uint32_t* bb){
    asm volatile(
      "mma.sync.aligned.m16n8k8.row.col.f32.tf32.tf32.f32 "
      "{%0,%1,%2,%3}, {%4,%5,%6,%7}, {%8,%9}, {%0,%1,%2,%3};"
      : "+f"(d[0]),"+f"(d[1]),"+f"(d[2]),"+f"(d[3])
      : "r"(a[0]),"r"(a[1]),"r"(a[2]),"r"(a[3]),"r"(bb[0]),"r"(bb[1]));
}

// ---------------------------------------------------------------------------
// Prep kernels
// ---------------------------------------------------------------------------
// w_out [576][128] -> tf32, padded layout [ch][kk*SB + n] (n>=128 zero)
__global__ void prep_wp_kernel(const float* __restrict__ w_out)
{
    int idx = blockIdx.x * 256 + threadIdx.x;   // 18*BBUF = 78336
    if (idx >= 18*BBUF) return;
    int n  = idx % SB;
    int kk = (idx / SB) & 31;
    int ch = idx / BBUF;
    float v = 0.f;
    if (n < 128) v = __uint_as_float(f2tf32(w_out[(ch*32 + kk)*128 + n]));
    g_wTp[idx] = v;
}
// w_off [dy][dx][c][oc] -> pairs [dydx][c][10]
__global__ void prep_woff2_kernel(const float* __restrict__ w_off)
{
    int idx = blockIdx.x * 256 + threadIdx.x;   // 5760
    if (idx >= 5760) return;
    int p    = idx % 10;
    int c    = (idx / 10) % 64;
    int dydx = idx / 640;
    float2 v = make_float2(0.f, 0.f);
    if (p < 9) {
        v.x = w_off[(dydx*64 + c)*18 + 2*p];
        v.y = w_off[(dydx*64 + c)*18 + 2*p + 1];
    }
    g_wOff2[idx] = v;
}
// x [b][y][x][c] -> g_xT [b][cb][y][x]
__global__ __launch_bounds__(256) void transpose_x(const float4* __restrict__ x4)
{
    const int blk  = blockIdx.x;
    const int px   = threadIdx.x & 127;
    const int half = threadIdx.x >> 7;
    const int b = blk >> 7, y = blk & 127;
    const int pix16 = (blk * 128 + px) * 16;
    #pragma unroll
    for (int q = 0; q < 8; q++) {
        int cb = half * 8 + q;
        g_xT[((b*16 + cb) << 14) + y*128 + px] = x4[pix16 + cb];
    }
}

// ---------------------------------------------------------------------------
// Kernel 1: 3x3 SAME conv 64->18, fp32 f32x2, channel-split across 2 halves.
// Weights staged PER-DY (15.4 KB) -> smem 49.7 KB -> 4 blocks/SM (occ 48%).
// ---------------------------------------------------------------------------
#define ROWF   (130*66)
#define WSLICE (3*64*10)                        // 1920 u64 per dy slice
#define SM1_TOTAL ((ROWF + WSLICE*2) * 4)       // 49680 B

__global__ __launch_bounds__(256) void offset_conv_kernel(
    const float* __restrict__ x, const float* __restrict__ b_off)
{
    extern __shared__ float sm1[];
    float* row = sm1;                                        // [130][66]
    unsigned long long* wsh = (unsigned long long*)(sm1 + ROWF);  // 1920 u64

    const int t  = threadIdx.x;
    const int pm = t & 127;
    const int th = t >> 7;                 // channel half: 0 -> c<32, 1 -> c>=32
    const int by = blockIdx.x;
    const int b  = by >> 7;
    const int y  = by & 127;

    unsigned long long acc[9];
    #pragma unroll
    for (int p = 0; p < 9; p++)
        acc[p] = th ? pack2(0.f, 0.f) : pack2(b_off[2*p], b_off[2*p+1]);

    for (int dy = 0; dy < 3; dy++) {
        __syncthreads();                   // protect previous iter's reads
        const int yy = y + dy - 1;

        // stage this dy's weight slice (1920 u64 = 15.4 KB)
        {
            const unsigned long long* src =
                (const unsigned long long*)g_wOff2 + dy * WSLICE;
            #pragma unroll
            for (int i = 0; i < WSLICE/256; i += 1)   // 1920/256 = 7.5 -> loop
                ;
            for (int i = t; i < WSLICE; i += 256) wsh[i] = src[i];
        }

        if (t < 2) {                       // zero horizontal pads (full 64 ch)
            const int e = (t == 0) ? 0 : 129;
            float2* z = (float2*)&row[e * 66];
            #pragma unroll
            for (int i = 0; i < 32; i++) z[i] = make_float2(0.f, 0.f);
        }
        {
            float2* dst = (float2*)&row[(pm + 1) * 66] + th * 16;
            if (yy >= 0 && yy < 128) {
                const float4* src =
                    (const float4*)&x[((b * H_ + yy) * W_ + pm) * C_ + th * 32];
                #pragma unroll
                for (int i = 0; i < 8; i++) {
                    float4 v = src[i];
                    dst[2*i]   = make_float2(v.x, v.y);
                    dst[2*i+1] = make_float2(v.z, v.w);
                }
            } else {
                #pragma unroll
                for (int i = 0; i < 16; i++) dst[i] = make_float2(0.f, 0.f);
            }
        }
        __syncthreads();

        #pragma unroll
        for (int dx = 0; dx < 3; dx++) {
            const float* rowp = &row[(pm + dx) * 66 + th * 32];
            const unsigned long long* wdx = wsh + dx * 640 + th * 320;
            #pragma unroll 4
            for (int c = 0; c < 32; c += 2) {
                const float2 rv = *(const float2*)&rowp[c];
                const unsigned long long ax = pack2(rv.x, rv.x);
                const unsigned long long ay = pack2(rv.y, rv.y);
                const unsigned long long* wx = wdx + c * 10;
                const unsigned long long* wy = wx + 10;
                #pragma unroll
                for (int p = 0; p < 9; p++) ffma2(acc[p], ax, wx[p]);
                #pragma unroll
                for (int p = 0; p < 9; p++) ffma2(acc[p], ay, wy[p]);
            }
        }
    }

    // cross-half reduction (reuse row area)
    __syncthreads();
    unsigned long long* red = (unsigned long long*)row;   // 128*10 u64
    if (th == 1) {
        #pragma unroll
        for (int p = 0; p < 9; p++) red[pm*10 + p] = acc[p];
    }
    __syncthreads();
    if (th == 0) {
        float2* op = (float2*)&g_offsets[((b * H_ + y) * W_ + pm) * 18];
        #pragma unroll
        for (int p = 0; p < 9; p++) {
            addf2(acc[p], red[pm*10 + p]);
            float lo, hi;
            asm("mov.b64 {%0,%1}, %2;" : "=f"(lo), "=f"(hi) : "l"(acc[p]));
            op[p] = make_float2(lo, hi);
        }
    }
}

// ---------------------------------------------------------------------------
// Kernel 2: fused bilinear sampling + tf32 mma GEMM (round-10, unchanged)
// ---------------------------------------------------------------------------
#define SM2_TOTAL ((2*ABUF + 2*BBUF)*4)     // 53248 B

__global__ __launch_bounds__(256, 2) void dconv_gemm_mma(
    const float* __restrict__ b_out, float* __restrict__ out)
{
    extern __shared__ float sm[];
    float* Abuf[2] = { sm, sm + ABUF };
    float* Bbuf[2] = { sm + 2*ABUF, sm + 2*ABUF + BBUF };
    const uint32_t Bu = smem_u32(sm + 2*ABUF);

    const int tid  = threadIdx.x;
    const int wid  = tid >> 5;
    const int lane = tid & 31;
    const int g  = lane >> 2;
    const int tc = lane & 3;

    const int p0 = blockIdx.x * 64;
    const int b  = p0 >> 14;
    const int y  = (p0 >> 7) & 127;
    const int x0 = p0 & 127;
    const int pm = tid & 63;
    const int h  = tid >> 6;
    const int gx = x0 + pm;

    const int m_base = (wid >> 2) * 32;
    const int n_base = (wid & 3) * 32;
    const float* offp = &g_offsets[(p0 + pm) * 18];

    float acc[2][4][4];
    #pragma unroll
    for (int nf = 0; nf < 4; nf++) {
        const int c0 = n_base + nf*8 + 2*tc;
        const float bz0 = __ldg(&b_out[c0]), bz1 = __ldg(&b_out[c0+1]);
        #pragma unroll
        for (int mf = 0; mf < 2; mf++) {
            acc[mf][nf][0] = bz0; acc[mf][nf][1] = bz1;
            acc[mf][nf][2] = bz0; acc[mf][nf][3] = bz1;
        }
    }

    float wa=0.f, wbv=0.f, wcv=0.f, wdv=0.f;
    int i00=0, i10=0, i01=0, i11=0;

    #define COORDS(off) { \
        float nx = fminf(fmaxf((float)gx + (off).x, 0.f), 127.f); \
        float ny = fminf(fmaxf((float)y  + (off).y, 0.f), 127.f); \
        float x0f = floorf(nx), y0f = floorf(ny); \
        float x1f = fminf(x0f + 1.f, 127.f), y1f = fminf(y0f + 1.f, 127.f); \
        float lx = nx - x0f, hx = x1f - nx; \
        float ly = ny - y0f, hy = y1f - ny; \
        wa = hx*hy; wbv = hx*ly; wcv = lx*hy; wdv = lx*ly; \
        int ix0 = (int)x0f, ix1 = (int)x1f, iy0 = (int)y0f, iy1 = (int)y1f; \
        i00 = iy0*128 + ix0;  i10 = iy1*128 + ix0; \
        i01 = iy0*128 + ix1;  i11 = iy1*128 + ix1; }

    float4 a0,b0,c0_,d0, a1,b1,c1_,d1;     // both planes of corners
    uint32_t vv[8];

    #define GATHER2(chv) { \
        const int cb = (b*16 + ((chv)&1)*8 + h*2) << 14; \
        a0 = g_xT[cb + i00]; b0 = g_xT[cb + i10]; \
        c0_ = g_xT[cb + i01]; d0 = g_xT[cb + i11]; \
        const int cb1 = cb + (1 << 14); \
        a1 = g_xT[cb1 + i00]; b1 = g_xT[cb1 + i10]; \
        c1_ = g_xT[cb1 + i01]; d1 = g_xT[cb1 + i11]; }

    #define WEIGHT2() { \
        vv[0] = f2tf32(wa*a0.x + wbv*b0.x + wcv*c0_.x + wdv*d0.x); \
        vv[1] = f2tf32(wa*a0.y + wbv*b0.y + wcv*c0_.y + wdv*d0.y); \
        vv[2] = f2tf32(wa*a0.z + wbv*b0.z + wcv*c0_.z + wdv*d0.z); \
        vv[3] = f2tf32(wa*a0.w + wbv*b0.w + wcv*c0_.w + wdv*d0.w); \
        vv[4] = f2tf32(wa*a1.x + wbv*b1.x + wcv*c1_.x + wdv*d1.x); \
        vv[5] = f2tf32(wa*a1.y + wbv*b1.y + wcv*c1_.y + wdv*d1.y); \
        vv[6] = f2tf32(wa*a1.z + wbv*b1.z + wcv*c1_.z + wdv*d1.z); \
        vv[7] = f2tf32(wa*a1.w + wbv*b1.w + wcv*c1_.w + wdv*d1.w); }

    #define CPB(chv, pbuf) { \
        const uint32_t dbase = Bu + (uint32_t)(pbuf) * (BBUF*4u); \
        const char* srcb = (const char*)&g_wTp[(chv) * BBUF]; \
        _Pragma("unroll") \
        for (int i = 0; i < 5; i++) { \
            int idx = tid + i*256; \
            if (idx < 1088) cpasync16(dbase + (uint32_t)idx*16u, srcb + idx*16); \
        } }

    #define MMASTEP(s, Ab, Bb) { \
        const int k0 = (s) * 8; \
        const uint32_t* Ar0 = (const uint32_t*)&(Ab)[(k0 + tc)     * SA2]; \
        const uint32_t* Ar1 = (const uint32_t*)&(Ab)[(k0 + tc + 4) * SA2]; \
        const uint32_t* Br0 = (const uint32_t*)&(Bb)[(k0 + tc)     * SB]; \
        const uint32_t* Br1 = (const uint32_t*)&(Bb)[(k0 + tc + 4) * SB]; \
        uint32_t afr[2][4]; \
        _Pragma("unroll") \
        for (int mf = 0; mf < 2; mf++) { \
            const int m = m_base + mf*16 + g; \
            afr[mf][0] = Ar0[m];  afr[mf][1] = Ar0[m+8]; \
            afr[mf][2] = Ar1[m];  afr[mf][3] = Ar1[m+8]; \
        } \
        uint32_t bfr[4][2]; \
        _Pragma("unroll") \
        for (int nf = 0; nf < 4; nf++) { \
            const int n = n_base + nf*8 + g; \
            bfr[nf][0] = Br0[n];  bfr[nf][1] = Br1[n]; \
        } \
        _Pragma("unroll") \
        for (int mf = 0; mf < 2; mf++) \
            _Pragma("unroll") \
            for (int nf = 0; nf < 4; nf++) \
                mma_tf32(acc[mf][nf], afr[mf], bfr[nf]); }

    // ---- prologue ----
    float2 curoff  = *(const float2*)(offp + 0);
    float2 nextoff = *(const float2*)(offp + 2);
    COORDS(curoff);
    GATHER2(0);
    WEIGHT2();                      // vv = A(0); stalls on first gathers only
    CPB(0, 0); CP_COMMIT();         // B(0) in flight

    for (int ch = 0; ch < 18; ch++) {
        const int p = ch & 1;
        float* Ab = Abuf[p];
        float* Bb = Bbuf[p];

        // 1. store A(ch) from vv
        #pragma unroll
        for (int j = 0; j < 2; j++) {
            const int k = h*8 + j*4;
            Ab[(k+0)*SA2 + pm] = __uint_as_float(vv[j*4+0]);
            Ab[(k+1)*SA2 + pm] = __uint_as_float(vv[j*4+1]);
            Ab[(k+2)*SA2 + pm] = __uint_as_float(vv[j*4+2]);
            Ab[(k+3)*SA2 + pm] = __uint_as_float(vv[j*4+3]);
        }

        // 2. B(ch) must have landed; publish A(ch)+B(ch)
        CP_WAIT0();
        __syncthreads();

        const bool more = (ch + 1 < 18);
        // 3. issue next chunk's gathers + B copy (hidden behind MMA phase)
        if (more) {
            if (((ch + 1) & 1) == 0) {
                COORDS(nextoff);
                if (ch + 1 <= 14)
                    nextoff = *(const float2*)(offp + ((ch+3) >> 1) * 2);
            }
            GATHER2(ch + 1);
            CPB(ch + 1, p ^ 1); CP_COMMIT();
        }

        // 4. full MMA phase on chunk ch
        MMASTEP(0, Ab, Bb);
        MMASTEP(1, Ab, Bb);
        MMASTEP(2, Ab, Bb);
        MMASTEP(3, Ab, Bb);

        // 5. weight+convert next chunk's samples
        if (more) { WEIGHT2(); }
    }

    // ---- epilogue ----
    #pragma unroll
    for (int mf = 0; mf < 2; mf++) {
        const int row = p0 + m_base + mf*16 + g;
        #pragma unroll
        for (int nf = 0; nf < 4; nf++) {
            const int col = n_base + nf*8 + 2*tc;
            *(float2*)&out[(size_t)row * F_ + col] =
                make_float2(acc[mf][nf][0], acc[mf][nf][1]);
            *(float2*)&out[(size_t)(row + 8) * F_ + col] =
                make_float2(acc[mf][nf][2], acc[mf][nf][3]);
        }
    }
}

// ---------------------------------------------------------------------------
extern "C" void kernel_launch(void* const* d_in, const int* in_sizes, int n_in,
                              void* d_out, int out_size)
{
    const float* x     = (const float*)d_in[0];
    const float* w_off = (const float*)d_in[1];
    const float* b_off = (const float*)d_in[2];
    const float* w_out = (const float*)d_in[3];
    const float* b_out = (const float*)d_in[4];
    float* out = (float*)d_out;

    cudaFuncSetAttribute(offset_conv_kernel,
                         cudaFuncAttributeMaxDynamicSharedMemorySize, SM1_TOTAL);
    cudaFuncSetAttribute(dconv_gemm_mma,
                         cudaFuncAttributeMaxDynamicSharedMemorySize, SM2_TOTAL);

    prep_wp_kernel    <<<(18*BBUF + 255)/256, 256>>>(w_out);
    prep_woff2_kernel <<<(5760 + 255)/256, 256>>>(w_off);
    transpose_x       <<<B_ * H_, 256>>>((const float4*)x);
    offset_conv_kernel<<<B_ * H_, 256, SM1_TOTAL>>>(x, b_off);
    dconv_gemm_mma    <<<(B_*H_*W_)/64, 256, SM2_TOTAL>>>(b_out, out);
}